// round 9
// baseline (speedup 1.0000x reference)
#include <cuda_runtime.h>
#include <cstdint>

#define BATCH 4
#define SEQ   2048
#define DIN   1024
#define DQ    1024
#define DV    1024

// Scratch (allocation-free rule: __device__ globals)
__device__ float g_q[(size_t)BATCH * SEQ * DQ];
__device__ float g_k[(size_t)BATCH * SEQ * DQ];
__device__ float g_v[(size_t)BATCH * SEQ * DV];
__device__ float g_p[(size_t)BATCH * SEQ * SEQ];
// rounded-input scratch: 3 activations (8.4M ea) + 3 weights (1M ea)
__device__ float g_r[(size_t)3 * BATCH * SEQ * DIN + 3 * (size_t)DQ * DIN];

#define RQ_OFF  ((size_t)0)
#define RK_OFF  ((size_t)BATCH * SEQ * DIN)
#define RV_OFF  ((size_t)2 * BATCH * SEQ * DIN)
#define RWQ_OFF ((size_t)3 * BATCH * SEQ * DIN)
#define RWK_OFF (RWQ_OFF + (size_t)DQ * DIN)
#define RWV_OFF (RWK_OFF + (size_t)DQ * DIN)

__device__ __forceinline__ uint32_t f2tf32(float x) {
    uint32_t r;
    asm("cvt.rna.tf32.f32 %0, %1;" : "=r"(r) : "f"(x));
    return r;
}

__device__ __forceinline__ void mma8(float* c, const uint32_t* a, const uint32_t* b) {
    asm volatile(
        "mma.sync.aligned.m16n8k8.row.col.f32.tf32.tf32.f32 "
        "{%0,%1,%2,%3}, {%4,%5,%6,%7}, {%8,%9}, {%0,%1,%2,%3};"
        : "+f"(c[0]), "+f"(c[1]), "+f"(c[2]), "+f"(c[3])
        : "r"(a[0]), "r"(a[1]), "r"(a[2]), "r"(a[3]), "r"(b[0]), "r"(b[1]));
}

__device__ __forceinline__ void cpa16(float* s, const float* g) {
    unsigned sa = (unsigned)__cvta_generic_to_shared(s);
    asm volatile("cp.async.cg.shared.global [%0], [%1], 16;" :: "r"(sa), "l"(g));
}
__device__ __forceinline__ void cpa_commit() { asm volatile("cp.async.commit_group;"); }
__device__ __forceinline__ void cpa_wait0()  { asm volatile("cp.async.wait_group 0;"); }
__device__ __forceinline__ void cpa_wait1()  { asm volatile("cp.async.wait_group 1;"); }

__device__ __forceinline__ uint32_t ldsu(const float* p) {
    return __float_as_uint(*p);   // operands pre-rounded to tf32 grid: no cvt needed
}

// ===========================================================================
// RNA-round fp32 -> tf32-exact fp32 (one-time pre-pass)
// ===========================================================================
__global__ void round_tf32_kernel(const float* __restrict__ in, float* __restrict__ out)
{
    long i = ((long)blockIdx.x * 256 + threadIdx.x) * 4;
    float4 v = *(const float4*)(in + i);
    v.x = __uint_as_float(f2tf32(v.x));
    v.y = __uint_as_float(f2tf32(v.y));
    v.z = __uint_as_float(f2tf32(v.z));
    v.w = __uint_as_float(f2tf32(v.w));
    *(float4*)(out + i) = v;
}

// ---------------------------------------------------------------------------
// GEMM NT: C[m][n] = sum_k A[m][k] * B[n][k]  (+ epilogue).
// 3-stage cp.async pipeline, ONE __syncthreads per k-tile.
// Tiles: BM=BN=128, BK=32. 256 threads, 8 warps (2x4), warp tile 64x32.
// Stage = A[128][36] + B[128][36] = 9216 floats. 3 stages = 110592 B.
// ---------------------------------------------------------------------------
#define NT_STG 9216

__device__ __forceinline__ void nt_load(float* sm, int st, int tid,
                                        const float* Ab, const float* Bb,
                                        int k0, int K)
{
    float* sA = sm + st * NT_STG;
    float* sB = sA + 4608;
#pragma unroll
    for (int i = 0; i < 4; i++) {
        int idx = i * 256 + tid;
        int r = idx >> 3, c = (idx & 7) << 2;
        cpa16(&sA[r * 36 + c], Ab + (long)r * K + k0 + c);
        cpa16(&sB[r * 36 + c], Bb + (long)r * K + k0 + c);
    }
    cpa_commit();
}

__global__ __launch_bounds__(256, 2)
void gemm_nt_kernel(const float* __restrict__ A, long sAz,
                    const float* __restrict__ B, long sBz,
                    const float* __restrict__ bias,
                    const int* __restrict__ mask, long sMz,
                    float* __restrict__ C, long sCz,
                    int N, int K, float scale, int epi)
{
    extern __shared__ float sm[];

    const int tid  = threadIdx.x;
    const int lane = tid & 31, warp = tid >> 5;
    const int wm = warp >> 2, wn = warp & 3;   // 2 x 4 warp grid
    const int gq = lane >> 2, tg = lane & 3;

    const float* Ab = A + (long)blockIdx.z * sAz + (long)blockIdx.y * 128 * K;
    const float* Bb = B + (long)blockIdx.z * sBz + (long)blockIdx.x * 128 * K;

    float acc[4][4][4];
#pragma unroll
    for (int i = 0; i < 4; i++)
#pragma unroll
        for (int j = 0; j < 4; j++)
#pragma unroll
            for (int l = 0; l < 4; l++) acc[i][j][l] = 0.f;

    const int NIT = K >> 5;

    nt_load(sm, 0, tid, Ab, Bb, 0, K);
    nt_load(sm, 1, tid, Ab, Bb, 32, K);

    int st = 0;          // buffer for current compute tile
    int ld = 2;          // next buffer to load into
    for (int it = 0; it < NIT; ++it) {
        if (it + 1 < NIT) cpa_wait1(); else cpa_wait0();
        __syncthreads();
        if (it + 2 < NIT) {
            nt_load(sm, ld, tid, Ab, Bb, (it + 2) << 5, K);
            if (++ld == 3) ld = 0;
        }

        const float* cA = sm + st * NT_STG;
        const float* cB = cA + 4608;
        if (++st == 3) st = 0;
#pragma unroll
        for (int ks = 0; ks < 4; ++ks) {
            uint32_t af[4][4];
            uint32_t bf[4][2];
#pragma unroll
            for (int mt = 0; mt < 4; ++mt) {
                int r = wm * 64 + mt * 16 + gq;
                int c = ks * 8 + tg;
                af[mt][0] = ldsu(&cA[r * 36 + c]);
                af[mt][1] = ldsu(&cA[(r + 8) * 36 + c]);
                af[mt][2] = ldsu(&cA[r * 36 + c + 4]);
                af[mt][3] = ldsu(&cA[(r + 8) * 36 + c + 4]);
            }
#pragma unroll
            for (int nt = 0; nt < 4; ++nt) {
                int r = wn * 32 + nt * 8 + gq;
                int c = ks * 8 + tg;
                bf[nt][0] = ldsu(&cB[r * 36 + c]);
                bf[nt][1] = ldsu(&cB[r * 36 + c + 4]);
            }
#pragma unroll
            for (int mt = 0; mt < 4; ++mt)
#pragma unroll
                for (int nt = 0; nt < 4; ++nt)
                    mma8(acc[mt][nt], af[mt], bf[nt]);
        }
    }

    // epilogue
    C += (long)blockIdx.z * sCz;
    if (epi == 1) mask += (long)blockIdx.z * sMz;
#pragma unroll
    for (int mt = 0; mt < 4; ++mt) {
        int row = blockIdx.y * 128 + wm * 64 + mt * 16 + gq;
#pragma unroll
        for (int nt = 0; nt < 4; ++nt) {
            int col = blockIdx.x * 128 + wn * 32 + nt * 8 + tg * 2;
            float* a = acc[mt][nt];
            long r0 = (long)row * N, r1 = (long)(row + 8) * N;
            if (epi == 0) {
                float b0 = bias[col], b1 = bias[col + 1];
                C[r0 + col]     = __uint_as_float(f2tf32(a[0] + b0));
                C[r0 + col + 1] = __uint_as_float(f2tf32(a[1] + b1));
                C[r1 + col]     = __uint_as_float(f2tf32(a[2] + b0));
                C[r1 + col + 1] = __uint_as_float(f2tf32(a[3] + b1));
            } else {
                C[r0 + col]     = mask[r0 + col]     ? -1.0e9f : a[0] * scale;
                C[r0 + col + 1] = mask[r0 + col + 1] ? -1.0e9f : a[1] * scale;
                C[r1 + col]     = mask[r1 + col]     ? -1.0e9f : a[2] * scale;
                C[r1 + col + 1] = mask[r1 + col + 1] ? -1.0e9f : a[3] * scale;
            }
        }
    }
}

// ---------------------------------------------------------------------------
// GEMM NN: C[m][n] = sum_k A[m][k] * B[k][n]   (out = P @ V).
// 3-stage pipeline, one sync per k-tile. Stage = A 4608 + B 4224 = 8832 fl.
// ---------------------------------------------------------------------------
#define NN_STG 8832

__device__ __forceinline__ void nn_load(float* sm, int st, int tid,
                                        const float* Ab, const float* Bb,
                                        int k0, int K, int N)
{
    float* sA = sm + st * NN_STG;
    float* sB = sA + 4608;
#pragma unroll
    for (int i = 0; i < 4; i++) {
        int idx = i * 256 + tid;
        int ra = idx >> 3, ca = (idx & 7) << 2;
        cpa16(&sA[ra * 36 + ca], Ab + (long)ra * K + k0 + ca);
        int rb = idx >> 5, cb = (idx & 31) << 2;
        cpa16(&sB[rb * 132 + cb], Bb + (long)(k0 + rb) * N + cb);
    }
    cpa_commit();
}

__global__ __launch_bounds__(256, 2)
void gemm_nn_kernel(const float* __restrict__ A, long sAz,
                    const float* __restrict__ B, long sBz,
                    float* __restrict__ C, long sCz,
                    int N, int K)
{
    extern __shared__ float sm[];

    const int tid  = threadIdx.x;
    const int lane = tid & 31, warp = tid >> 5;
    const int wm = warp >> 2, wn = warp & 3;
    const int gq = lane >> 2, tg = lane & 3;

    const float* Ab = A + (long)blockIdx.z * sAz + (long)blockIdx.y * 128 * K;
    const float* Bb = B + (long)blockIdx.z * sBz + (long)blockIdx.x * 128;

    float acc[4][4][4];
#pragma unroll
    for (int i = 0; i < 4; i++)
#pragma unroll
        for (int j = 0; j < 4; j++)
#pragma unroll
            for (int l = 0; l < 4; l++) acc[i][j][l] = 0.f;

    const int NIT = K >> 5;

    nn_load(sm, 0, tid, Ab, Bb, 0, K, N);
    nn_load(sm, 1, tid, Ab, Bb, 32, K, N);

    int st = 0, ld = 2;
    for (int it = 0; it < NIT; ++it) {
        if (it + 1 < NIT) cpa_wait1(); else cpa_wait0();
        __syncthreads();
        if (it + 2 < NIT) {
            nn_load(sm, ld, tid, Ab, Bb, (it + 2) << 5, K, N);
            if (++ld == 3) ld = 0;
        }

        const float* cA = sm + st * NN_STG;
        const float* cB = cA + 4608;
        if (++st == 3) st = 0;
#pragma unroll
        for (int ks = 0; ks < 4; ++ks) {
            uint32_t af[4][4];
            uint32_t bf[4][2];
#pragma unroll
            for (int mt = 0; mt < 4; ++mt) {
                int r = wm * 64 + mt * 16 + gq;
                int c = ks * 8 + tg;
                af[mt][0] = ldsu(&cA[r * 36 + c]);
                af[mt][1] = ldsu(&cA[(r + 8) * 36 + c]);
                af[mt][2] = ldsu(&cA[r * 36 + c + 4]);
                af[mt][3] = ldsu(&cA[(r + 8) * 36 + c + 4]);
            }
#pragma unroll
            for (int nt = 0; nt < 4; ++nt) {
                int n = wn * 32 + nt * 8 + gq;
                int k = ks * 8 + tg;
                bf[nt][0] = ldsu(&cB[k * 132 + n]);
                bf[nt][1] = ldsu(&cB[(k + 4) * 132 + n]);
            }
#pragma unroll
            for (int mt = 0; mt < 4; ++mt)
#pragma unroll
                for (int nt = 0; nt < 4; ++nt)
                    mma8(acc[mt][nt], af[mt], bf[nt]);
        }
    }

    C += (long)blockIdx.z * sCz;
#pragma unroll
    for (int mt = 0; mt < 4; ++mt) {
        int row = blockIdx.y * 128 + wm * 64 + mt * 16 + gq;
#pragma unroll
        for (int nt = 0; nt < 4; ++nt) {
            int col = blockIdx.x * 128 + wn * 32 + nt * 8 + tg * 2;
            float* a = acc[mt][nt];
            long r0 = (long)row * N, r1 = (long)(row + 8) * N;
            C[r0 + col]     = a[0];
            C[r0 + col + 1] = a[1];
            C[r1 + col]     = a[2];
            C[r1 + col + 1] = a[3];
        }
    }
}

// ---------------------------------------------------------------------------
// Row softmax over P; writes tf32-rounded probabilities.
// ---------------------------------------------------------------------------
__global__ void softmax_kernel(float* __restrict__ P)
{
    float* p = P + (long)blockIdx.x * SEQ;
    const int tid = threadIdx.x;
    __shared__ float red[8];

    float v[8];
    float mx = -3.4e38f;
#pragma unroll
    for (int i = 0; i < 8; i++) {
        v[i] = p[tid + (i << 8)];
        mx = fmaxf(mx, v[i]);
    }
#pragma unroll
    for (int o = 16; o > 0; o >>= 1) mx = fmaxf(mx, __shfl_xor_sync(0xffffffffu, mx, o));
    if ((tid & 31) == 0) red[tid >> 5] = mx;
    __syncthreads();
    mx = red[0];
#pragma unroll
    for (int i = 1; i < 8; i++) mx = fmaxf(mx, red[i]);

    float sum = 0.f;
#pragma unroll
    for (int i = 0; i < 8; i++) {
        v[i] = expf(v[i] - mx);
        sum += v[i];
    }
#pragma unroll
    for (int o = 16; o > 0; o >>= 1) sum += __shfl_xor_sync(0xffffffffu, sum, o);
    __syncthreads();
    if ((tid & 31) == 0) red[tid >> 5] = sum;
    __syncthreads();
    float tot = 0.f;
#pragma unroll
    for (int i = 0; i < 8; i++) tot += red[i];
    float inv = 1.0f / tot;
#pragma unroll
    for (int i = 0; i < 8; i++)
        p[tid + (i << 8)] = __uint_as_float(f2tf32(v[i] * inv));
}

// ---------------------------------------------------------------------------
extern "C" void kernel_launch(void* const* d_in, const int* in_sizes, int n_in,
                              void* d_out, int out_size)
{
    const float* query = (const float*)d_in[0];
    const float* key   = (const float*)d_in[1];
    const float* value = (const float*)d_in[2];
    const int*   mask  = (const int*)d_in[3];     // bool stored as int32
    const float* Wq = (const float*)d_in[4];
    const float* bq = (const float*)d_in[5];
    const float* Wk = (const float*)d_in[6];
    const float* bk = (const float*)d_in[7];
    const float* Wv = (const float*)d_in[8];
    const float* bv = (const float*)d_in[9];
    float* out = (float*)d_out;

    float *qb, *kb, *vb, *pb, *rb;
    cudaGetSymbolAddress((void**)&qb, g_q);
    cudaGetSymbolAddress((void**)&kb, g_k);
    cudaGetSymbolAddress((void**)&vb, g_v);
    cudaGetSymbolAddress((void**)&pb, g_p);
    cudaGetSymbolAddress((void**)&rb, g_r);

    const int SMEM_NT = 3 * NT_STG * 4;   // 110592 B
    const int SMEM_NN = 3 * NN_STG * 4;   // 105984 B
    cudaFuncSetAttribute(gemm_nt_kernel, cudaFuncAttributeMaxDynamicSharedMemorySize, SMEM_NT);
    cudaFuncSetAttribute(gemm_nn_kernel, cudaFuncAttributeMaxDynamicSharedMemorySize, SMEM_NN);

    // one-time RNA rounding of all projection-GEMM inputs (scratch in g_r)
    const long NACT = (long)BATCH * SEQ * DIN;   // 8388608
    round_tf32_kernel<<<NACT / 1024, 256>>>(query, rb + RQ_OFF);
    round_tf32_kernel<<<NACT / 1024, 256>>>(key,   rb + RK_OFF);
    round_tf32_kernel<<<NACT / 1024, 256>>>(value, rb + RV_OFF);
    round_tf32_kernel<<<(DQ * DIN) / 1024, 256>>>(Wq, rb + RWQ_OFF);
    round_tf32_kernel<<<(DQ * DIN) / 1024, 256>>>(Wk, rb + RWK_OFF);
    round_tf32_kernel<<<(DV * DIN) / 1024, 256>>>(Wv, rb + RWV_OFF);

    dim3 blk(256);

    // QKV projections: M = B*S = 8192, N = 1024, K = 1024
    dim3 gp(DQ / 128, (BATCH * SEQ) / 128, 1);
    gemm_nt_kernel<<<gp, blk, SMEM_NT>>>(rb + RQ_OFF, 0, rb + RWQ_OFF, 0, bq,
                                         nullptr, 0, qb, 0, DQ, DIN, 0.f, 0);
    gemm_nt_kernel<<<gp, blk, SMEM_NT>>>(rb + RK_OFF, 0, rb + RWK_OFF, 0, bk,
                                         nullptr, 0, kb, 0, DQ, DIN, 0.f, 0);
    gemm_nt_kernel<<<gp, blk, SMEM_NT>>>(rb + RV_OFF, 0, rb + RWV_OFF, 0, bv,
                                         nullptr, 0, vb, 0, DV, DIN, 0.f, 0);

    // scores: per batch M = N = SEQ, K = DQ, scale = 1/sqrt(1024)
    dim3 gs(SEQ / 128, SEQ / 128, BATCH);
    gemm_nt_kernel<<<gs, blk, SMEM_NT>>>(qb, (long)SEQ * DQ, kb, (long)SEQ * DQ,
                                         nullptr, mask, (long)SEQ * SEQ,
                                         pb, (long)SEQ * SEQ, SEQ, DQ, 0.03125f, 1);

    // softmax over rows
    softmax_kernel<<<BATCH * SEQ, 256>>>(pb);

    // out = P @ V : per batch M = SEQ, N = DV, K = SEQ
    dim3 ga(DV / 128, SEQ / 128, BATCH);
    gemm_nn_kernel<<<ga, blk, SMEM_NN>>>(pb, (long)SEQ * SEQ, vb, (long)SEQ * DV,
                                         out, (long)SEQ * DV, DV, SEQ);
}

// round 12
// speedup vs baseline: 1.6049x; 1.6049x over previous
#include <cuda_runtime.h>
#include <cuda_fp16.h>
#include <cstdint>

#define BATCH 4
#define SEQ   2048
#define DIN   1024
#define DQ    1024
#define DV    1024

// Scratch (allocation-free rule: __device__ globals).
// g_q/g_k/g_v hold fp16 q,k,v (reinterpreted). g_p holds fp32 scores.
__device__ float g_q[(size_t)BATCH * SEQ * DQ / 2];
__device__ float g_k[(size_t)BATCH * SEQ * DQ / 2];
__device__ float g_v[(size_t)BATCH * SEQ * DV / 2];
__device__ float g_p[(size_t)BATCH * SEQ * SEQ];
// g_r: fp16 converted inputs (28.3M halves) before scores; fp16 P (16.8M halves) after.
__device__ float g_r[(size_t)16 * 1024 * 1024];

#define RQ_OFF  ((size_t)0)
#define RK_OFF  ((size_t)BATCH * SEQ * DIN)
#define RV_OFF  ((size_t)2 * BATCH * SEQ * DIN)
#define RWQ_OFF ((size_t)3 * BATCH * SEQ * DIN)
#define RWK_OFF (RWQ_OFF + (size_t)DQ * DIN)
#define RWV_OFF (RWK_OFF + (size_t)DQ * DIN)

__device__ __forceinline__ void mma16(float* c, const uint32_t* a, const uint32_t* b) {
    asm volatile(
        "mma.sync.aligned.m16n8k16.row.col.f32.f16.f16.f32 "
        "{%0,%1,%2,%3}, {%4,%5,%6,%7}, {%8,%9}, {%0,%1,%2,%3};"
        : "+f"(c[0]), "+f"(c[1]), "+f"(c[2]), "+f"(c[3])
        : "r"(a[0]), "r"(a[1]), "r"(a[2]), "r"(a[3]), "r"(b[0]), "r"(b[1]));
}

__device__ __forceinline__ void cpa16(void* s, const void* g) {
    unsigned sa = (unsigned)__cvta_generic_to_shared(s);
    asm volatile("cp.async.cg.shared.global [%0], [%1], 16;" :: "r"(sa), "l"(g));
}
__device__ __forceinline__ void cpa_commit() { asm volatile("cp.async.commit_group;"); }
__device__ __forceinline__ void cpa_wait0()  { asm volatile("cp.async.wait_group 0;"); }
__device__ __forceinline__ void cpa_wait1()  { asm volatile("cp.async.wait_group 1;"); }

// ===========================================================================
// fp32 -> fp16 conversion pre-pass (4 floats / thread)
// ===========================================================================
__global__ void cvt_half_kernel(const float* __restrict__ in, __half* __restrict__ out)
{
    long i = ((long)blockIdx.x * 256 + threadIdx.x) * 4;
    float4 v = *(const float4*)(in + i);
    __half2 h0 = __floats2half2_rn(v.x, v.y);
    __half2 h1 = __floats2half2_rn(v.z, v.w);
    uint2 pk;
    pk.x = *(uint32_t*)&h0;
    pk.y = *(uint32_t*)&h1;
    *(uint2*)(out + i) = pk;
}

// ---------------------------------------------------------------------------
// GEMM NT (fp16 in, fp32 acc): C[m][n] = sum_k A[m][k]*B[n][k] (+ epilogue)
//   epi 0: Ch = half(acc + bias[n])       (projections -> fp16 q/k/v)
//   epi 1: Cf = mask ? -1e9 : acc*scale   (scores -> fp32 P)
// Tiles BM=BN=128, BK=32. 8 warps (2x4), warp tile 64x32, m16n8k16.
// Smem rows: 32 data halves padded to 40 (word-stride 20 -> conflict-free).
// Stage = (128*40)*2 halves = 20480 B; 3 stages.
// ---------------------------------------------------------------------------
#define NTH_STG 10240   // halves per stage (A 5120 + B 5120)

__device__ __forceinline__ void nth_load(__half* sm, int st, int tid,
                                         const __half* Ab, const __half* Bb,
                                         int k0, int K)
{
    __half* sA = sm + (size_t)st * NTH_STG;
    __half* sB = sA + 5120;
#pragma unroll
    for (int i = 0; i < 4; i++) {
        int idx = i * 256 + tid;                 // 0..1023
        int r = (idx & 511) >> 2, c = idx & 3;   // row, 16B-chunk (8 halves)
        if (idx < 512)
            cpa16(sA + r * 40 + c * 8, Ab + (long)r * K + k0 + c * 8);
        else
            cpa16(sB + r * 40 + c * 8, Bb + (long)r * K + k0 + c * 8);
    }
    cpa_commit();
}

__global__ __launch_bounds__(256, 2)
void gemm_nt_h(const __half* __restrict__ A, long sAz,
               const __half* __restrict__ B, long sBz,
               const float* __restrict__ bias,
               const int* __restrict__ mask, long sMz,
               float* __restrict__ Cf, __half* __restrict__ Ch, long sCz,
               int N, int K, float scale, int epi)
{
    extern __shared__ __half smh[];

    const int tid  = threadIdx.x;
    const int lane = tid & 31, warp = tid >> 5;
    const int wm = warp >> 2, wn = warp & 3;     // 2 x 4 warp grid
    const int gq = lane >> 2, tg = lane & 3;

    const __half* Ab = A + (long)blockIdx.z * sAz + (long)blockIdx.y * 128 * K;
    const __half* Bb = B + (long)blockIdx.z * sBz + (long)blockIdx.x * 128 * K;

    float acc[4][4][4];
#pragma unroll
    for (int i = 0; i < 4; i++)
#pragma unroll
        for (int j = 0; j < 4; j++)
#pragma unroll
            for (int l = 0; l < 4; l++) acc[i][j][l] = 0.f;

    const int NIT = K >> 5;

    nth_load(smh, 0, tid, Ab, Bb, 0, K);
    nth_load(smh, 1, tid, Ab, Bb, 32, K);

    int st = 0, ld = 2;
    for (int it = 0; it < NIT; ++it) {
        if (it + 1 < NIT) cpa_wait1(); else cpa_wait0();
        __syncthreads();
        if (it + 2 < NIT) {
            nth_load(smh, ld, tid, Ab, Bb, (it + 2) << 5, K);
            if (++ld == 3) ld = 0;
        }

        const uint32_t* wA = (const uint32_t*)(smh + (size_t)st * NTH_STG);
        const uint32_t* wB = (const uint32_t*)(smh + (size_t)st * NTH_STG + 5120);
        if (++st == 3) st = 0;

#pragma unroll
        for (int ks = 0; ks < 2; ++ks) {         // two k16 steps per BK=32
            uint32_t af[4][4];
            uint32_t bf[4][2];
#pragma unroll
            for (int mt = 0; mt < 4; ++mt) {
                int r0 = wm * 64 + mt * 16 + gq;
                int w0 = r0 * 20 + ks * 8 + tg;
                af[mt][0] = wA[w0];
                af[mt][1] = wA[w0 + 160];        // +8 rows
                af[mt][2] = wA[w0 + 4];
                af[mt][3] = wA[w0 + 164];
            }
#pragma unroll
            for (int nt = 0; nt < 4; ++nt) {
                int rb = wn * 32 + nt * 8 + gq;
                int w0 = rb * 20 + ks * 8 + tg;
                bf[nt][0] = wB[w0];
                bf[nt][1] = wB[w0 + 4];
            }
#pragma unroll
            for (int mt = 0; mt < 4; ++mt)
#pragma unroll
                for (int nt = 0; nt < 4; ++nt)
                    mma16(acc[mt][nt], af[mt], bf[nt]);
        }
    }

    // epilogue
#pragma unroll
    for (int mt = 0; mt < 4; ++mt) {
        int row = blockIdx.y * 128 + wm * 64 + mt * 16 + gq;
#pragma unroll
        for (int nt = 0; nt < 4; ++nt) {
            int col = blockIdx.x * 128 + wn * 32 + nt * 8 + tg * 2;
            float* a = acc[mt][nt];
            long r0 = (long)row * N + col, r1 = (long)(row + 8) * N + col;
            if (epi == 0) {
                __half* C = Ch + (long)blockIdx.z * sCz;
                float b0 = bias[col], b1 = bias[col + 1];
                *(__half2*)(C + r0) = __floats2half2_rn(a[0] + b0, a[1] + b1);
                *(__half2*)(C + r1) = __floats2half2_rn(a[2] + b0, a[3] + b1);
            } else {
                float* C = Cf + (long)blockIdx.z * sCz;
                const int* M = mask + (long)blockIdx.z * sMz;
                C[r0]     = M[r0]     ? -1.0e9f : a[0] * scale;
                C[r0 + 1] = M[r0 + 1] ? -1.0e9f : a[1] * scale;
                C[r1]     = M[r1]     ? -1.0e9f : a[2] * scale;
                C[r1 + 1] = M[r1 + 1] ? -1.0e9f : a[3] * scale;
            }
        }
    }
}

// ---------------------------------------------------------------------------
// GEMM NN (fp16): C[m][n] = sum_k A[m][k] * B[k][n]   (out = P @ V, fp32 out)
// A tile rows of 40 halves; B tile [32][136 halves] (n-contiguous, padded).
// B fragments assembled from paired LDS.U16 (conflict-free per bank map).
// Stage = 5120 + 4352 = 9472 halves = 18944 B; 3 stages.
// ---------------------------------------------------------------------------
#define NNH_STG 9472

__device__ __forceinline__ void nnh_load(__half* sm, int st, int tid,
                                         const __half* Ab, const __half* Bb,
                                         int k0, int K, int N)
{
    __half* sA = sm + (size_t)st * NNH_STG;
    __half* sB = sA + 5120;
#pragma unroll
    for (int i = 0; i < 4; i++) {
        int idx = i * 256 + tid;
        if (idx < 512) {                          // A: 128 rows x 4 chunks
            int r = idx >> 2, c = idx & 3;
            cpa16(sA + r * 40 + c * 8, Ab + (long)r * K + k0 + c * 8);
        } else {                                  // B: 32 rows x 16 chunks
            int j = idx - 512;
            int r = j >> 4, c = j & 15;
            cpa16(sB + r * 136 + c * 8, Bb + (long)(k0 + r) * N + c * 8);
        }
    }
    cpa_commit();
}

__global__ __launch_bounds__(256, 2)
void gemm_nn_h(const __half* __restrict__ A, long sAz,
               const __half* __restrict__ B, long sBz,
               float* __restrict__ C, long sCz,
               int N, int K)
{
    extern __shared__ __half smh[];

    const int tid  = threadIdx.x;
    const int lane = tid & 31, warp = tid >> 5;
    const int wm = warp >> 2, wn = warp & 3;
    const int gq = lane >> 2, tg = lane & 3;

    const __half* Ab = A + (long)blockIdx.z * sAz + (long)blockIdx.y * 128 * K;
    const __half* Bb = B + (long)blockIdx.z * sBz + (long)blockIdx.x * 128;

    float acc[4][4][4];
#pragma unroll
    for (int i = 0; i < 4; i++)
#pragma unroll
        for (int j = 0; j < 4; j++)
#pragma unroll
            for (int l = 0; l < 4; l++) acc[i][j][l] = 0.f;

    const int NIT = K >> 5;

    nnh_load(smh, 0, tid, Ab, Bb, 0, K, N);
    nnh_load(smh, 1, tid, Ab, Bb, 32, K, N);

    int st = 0, ld = 2;
    for (int it = 0; it < NIT; ++it) {
        if (it + 1 < NIT) cpa_wait1(); else cpa_wait0();
        __syncthreads();
        if (it + 2 < NIT) {
            nnh_load(smh, ld, tid, Ab, Bb, (it + 2) << 5, K, N);
            if (++ld == 3) ld = 0;
        }

        const uint32_t* wA = (const uint32_t*)(smh + (size_t)st * NNH_STG);
        const unsigned short* hB = (const unsigned short*)(smh + (size_t)st * NNH_STG + 5120);
        if (++st == 3) st = 0;

#pragma unroll
        for (int ks = 0; ks < 2; ++ks) {
            uint32_t af[4][4];
            uint32_t bf[4][2];
#pragma unroll
            for (int mt = 0; mt < 4; ++mt) {
                int r0 = wm * 64 + mt * 16 + gq;
                int w0 = r0 * 20 + ks * 8 + tg;
                af[mt][0] = wA[w0];
                af[mt][1] = wA[w0 + 160];
                af[mt][2] = wA[w0 + 4];
                af[mt][3] = wA[w0 + 164];
            }
#pragma unroll
            for (int nt = 0; nt < 4; ++nt) {
                int n  = wn * 32 + nt * 8 + gq;
                int k0 = ks * 16 + 2 * tg;
                uint32_t l0 = hB[k0 * 136 + n];
                uint32_t h0 = hB[(k0 + 1) * 136 + n];
                uint32_t l1 = hB[(k0 + 8) * 136 + n];
                uint32_t h1 = hB[(k0 + 9) * 136 + n];
                bf[nt][0] = l0 | (h0 << 16);
                bf[nt][1] = l1 | (h1 << 16);
            }
#pragma unroll
            for (int mt = 0; mt < 4; ++mt)
#pragma unroll
                for (int nt = 0; nt < 4; ++nt)
                    mma16(acc[mt][nt], af[mt], bf[nt]);
        }
    }

    C += (long)blockIdx.z * sCz;
#pragma unroll
    for (int mt = 0; mt < 4; ++mt) {
        int row = blockIdx.y * 128 + wm * 64 + mt * 16 + gq;
#pragma unroll
        for (int nt = 0; nt < 4; ++nt) {
            int col = blockIdx.x * 128 + wn * 32 + nt * 8 + tg * 2;
            float* a = acc[mt][nt];
            long r0 = (long)row * N + col, r1 = (long)(row + 8) * N + col;
            C[r0]     = a[0];
            C[r0 + 1] = a[1];
            C[r1]     = a[2];
            C[r1 + 1] = a[3];
        }
    }
}

// ---------------------------------------------------------------------------
// Row softmax over fp32 scores P -> fp16 probabilities Ph.
// ---------------------------------------------------------------------------
__global__ void softmax_kernel(const float* __restrict__ P, __half* __restrict__ Ph)
{
    const float* p = P + (long)blockIdx.x * SEQ;
    __half* ph = Ph + (long)blockIdx.x * SEQ;
    const int tid = threadIdx.x;
    __shared__ float red[8];

    float v[8];
    float mx = -3.4e38f;
#pragma unroll
    for (int i = 0; i < 8; i++) {
        v[i] = p[tid + (i << 8)];
        mx = fmaxf(mx, v[i]);
    }
#pragma unroll
    for (int o = 16; o > 0; o >>= 1) mx = fmaxf(mx, __shfl_xor_sync(0xffffffffu, mx, o));
    if ((tid & 31) == 0) red[tid >> 5] = mx;
    __syncthreads();
    mx = red[0];
#pragma unroll
    for (int i = 1; i < 8; i++) mx = fmaxf(mx, red[i]);

    float sum = 0.f;
#pragma unroll
    for (int i = 0; i < 8; i++) {
        v[i] = expf(v[i] - mx);
        sum += v[i];
    }
#pragma unroll
    for (int o = 16; o > 0; o >>= 1) sum += __shfl_xor_sync(0xffffffffu, sum, o);
    __syncthreads();
    if ((tid & 31) == 0) red[tid >> 5] = sum;
    __syncthreads();
    float tot = 0.f;
#pragma unroll
    for (int i = 0; i < 8; i++) tot += red[i];
    float inv = 1.0f / tot;
#pragma unroll
    for (int i = 0; i < 8; i++)
        ph[tid + (i << 8)] = __float2half(v[i] * inv);
}

// ---------------------------------------------------------------------------
extern "C" void kernel_launch(void* const* d_in, const int* in_sizes, int n_in,
                              void* d_out, int out_size)
{
    const float* query = (const float*)d_in[0];
    const float* key   = (const float*)d_in[1];
    const float* value = (const float*)d_in[2];
    const int*   mask  = (const int*)d_in[3];     // bool stored as int32
    const float* Wq = (const float*)d_in[4];
    const float* bq = (const float*)d_in[5];
    const float* Wk = (const float*)d_in[6];
    const float* bk = (const float*)d_in[7];
    const float* Wv = (const float*)d_in[8];
    const float* bv = (const float*)d_in[9];
    float* out = (float*)d_out;

    void *qb, *kb, *vb, *pb, *rb;
    cudaGetSymbolAddress(&qb, g_q);
    cudaGetSymbolAddress(&kb, g_k);
    cudaGetSymbolAddress(&vb, g_v);
    cudaGetSymbolAddress(&pb, g_p);
    cudaGetSymbolAddress(&rb, g_r);
    __half* qh = (__half*)qb;
    __half* kh = (__half*)kb;
    __half* vh = (__half*)vb;
    float*  pf = (float*)pb;
    __half* rh = (__half*)rb;

    const int SMEM_NT = 3 * NTH_STG * 2;   // 61440 B
    const int SMEM_NN = 3 * NNH_STG * 2;   // 56832 B
    cudaFuncSetAttribute(gemm_nt_h, cudaFuncAttributeMaxDynamicSharedMemorySize, SMEM_NT);
    cudaFuncSetAttribute(gemm_nn_h, cudaFuncAttributeMaxDynamicSharedMemorySize, SMEM_NN);

    // fp32 -> fp16 conversion of all projection inputs (scratch in g_r)
    const long NACT = (long)BATCH * SEQ * DIN;   // 8388608
    cvt_half_kernel<<<NACT / 1024, 256>>>(query, rh + RQ_OFF);
    cvt_half_kernel<<<NACT / 1024, 256>>>(key,   rh + RK_OFF);
    cvt_half_kernel<<<NACT / 1024, 256>>>(value, rh + RV_OFF);
    cvt_half_kernel<<<(DQ * DIN) / 1024, 256>>>(Wq, rh + RWQ_OFF);
    cvt_half_kernel<<<(DQ * DIN) / 1024, 256>>>(Wk, rh + RWK_OFF);
    cvt_half_kernel<<<(DV * DIN) / 1024, 256>>>(Wv, rh + RWV_OFF);

    dim3 blk(256);

    // QKV projections: M = B*S = 8192, N = 1024, K = 1024 -> fp16 outputs
    dim3 gp(DQ / 128, (BATCH * SEQ) / 128, 1);
    gemm_nt_h<<<gp, blk, SMEM_NT>>>(rh + RQ_OFF, 0, rh + RWQ_OFF, 0, bq,
                                    nullptr, 0, nullptr, qh, 0, DQ, DIN, 0.f, 0);
    gemm_nt_h<<<gp, blk, SMEM_NT>>>(rh + RK_OFF, 0, rh + RWK_OFF, 0, bk,
                                    nullptr, 0, nullptr, kh, 0, DQ, DIN, 0.f, 0);
    gemm_nt_h<<<gp, blk, SMEM_NT>>>(rh + RV_OFF, 0, rh + RWV_OFF, 0, bv,
                                    nullptr, 0, nullptr, vh, 0, DV, DIN, 0.f, 0);

    // scores: per batch M = N = SEQ, K = DQ, scale = 1/sqrt(1024) -> fp32 P
    dim3 gs(SEQ / 128, SEQ / 128, BATCH);
    gemm_nt_h<<<gs, blk, SMEM_NT>>>(qh, (long)SEQ * DQ, kh, (long)SEQ * DQ,
                                    nullptr, mask, (long)SEQ * SEQ,
                                    pf, nullptr, (long)SEQ * SEQ, SEQ, DQ, 0.03125f, 1);

    // softmax over rows: fp32 scores -> fp16 probabilities (reuse g_r)
    softmax_kernel<<<BATCH * SEQ, 256>>>(pf, rh);

    // out = P @ V : per batch M = SEQ, N = DV, K = SEQ
    dim3 ga(DV / 128, SEQ / 128, BATCH);
    gemm_nn_h<<<ga, blk, SMEM_NN>>>(rh, (long)SEQ * SEQ, vh, (long)SEQ * DV,
                                    out, (long)SEQ * DV, DV, SEQ);
}